// round 15
// baseline (speedup 1.0000x reference)
#include <cuda_runtime.h>
#include <math.h>

#define MTAPS   41
#define OVERLAP 40
#define HOP     216
#define NFFT    256
#define PAD     20
#define BATCH   2
#define MAX_STEPS 4628
#define TWO_PI_F 6.283185307179586f

typedef unsigned long long ull;

__device__ float2 g_C[NFFT];   // C~[n] = (1/256) sum_m h[m] e^{-2 pi i n (m-20)/256}

__device__ __forceinline__ float2 cmulf(float2 a, float2 b) {
    return make_float2(fmaf(-a.y, b.y, a.x * b.x), fmaf(a.y, b.x, a.x * b.y));
}

// ======================= f32x2 packed primitives =======================
__device__ __forceinline__ ull pk2(float x, float y) {
    ull u; asm("mov.b64 %0, {%1,%2};" : "=l"(u) : "f"(x), "f"(y)); return u;
}
__device__ __forceinline__ float2 unpk(ull u) {
    float2 a; asm("mov.b64 {%0,%1}, %2;" : "=f"(a.x), "=f"(a.y) : "l"(u)); return a;
}
__device__ __forceinline__ ull splat(float x) { return pk2(x, x); }
__device__ __forceinline__ ull padd(ull a, ull b) {
    ull r; asm("add.rn.f32x2 %0, %1, %2;" : "=l"(r) : "l"(a), "l"(b)); return r;
}
__device__ __forceinline__ ull psub(ull a, ull b) {
    ull r; asm("sub.rn.f32x2 %0, %1, %2;" : "=l"(r) : "l"(a), "l"(b)); return r;
}
__device__ __forceinline__ ull pmul(ull a, ull b) {
    ull r; asm("mul.rn.f32x2 %0, %1, %2;" : "=l"(r) : "l"(a), "l"(b)); return r;
}
__device__ __forceinline__ ull pfma(ull a, ull b, ull c) {
    ull r; asm("fma.rn.f32x2 %0, %1, %2, %3;" : "=l"(r) : "l"(a), "l"(b), "l"(c)); return r;
}
#define C2P  0x3F3504F33F3504F3ULL
#define CN2P 0xBF3504F3BF3504F3ULL
#define ZP   0x0000000000000000ULL
#define RC2 0.70710678118654752440f

__device__ __forceinline__ ull pneg(ull a) { return psub(ZP, a); }
__device__ __forceinline__ ull pshfl_xor(ull v, int m) {
    unsigned lo = (unsigned)v, hi = (unsigned)(v >> 32);
    lo = __shfl_xor_sync(0xffffffffu, lo, m);
    hi = __shfl_xor_sync(0xffffffffu, hi, m);
    return ((ull)hi << 32) | (ull)lo;
}

// ======================= mode-packed complex (Re-pair, Im-pair) =======================
__device__ __forceinline__ void pcmul(ull& Re, ull& Im, float wx, float wy) {
    const ull sx = splat(wx), sy = splat(wy), syn = splat(-wy);
    const ull r = pfma(Re, sx, pmul(Im, syn));
    const ull i = pfma(Re, sy, pmul(Im, sx));
    Re = r; Im = i;
}
__device__ __forceinline__ void pW8_1(ull& Re, ull& Im) {
    const ull r = pmul(padd(Re, Im), (ull)C2P);
    const ull i = pmul(psub(Im, Re), (ull)C2P);
    Re = r; Im = i;
}
__device__ __forceinline__ void pW8_3(ull& Re, ull& Im) {
    const ull r = pmul(psub(Im, Re), (ull)C2P);
    const ull i = pmul(padd(Re, Im), (ull)CN2P);
    Re = r; Im = i;
}
__device__ __forceinline__ void pNI(ull& Re, ull& Im) { const ull r = Im; const ull i = pneg(Re); Re = r; Im = i; }
__device__ __forceinline__ void pPI(ull& Re, ull& Im) { const ull r = pneg(Im); const ull i = Re; Re = r; Im = i; }
__device__ __forceinline__ void pW8_1c(ull& Re, ull& Im) {
    const ull r = pmul(psub(Re, Im), (ull)C2P);
    const ull i = pmul(padd(Re, Im), (ull)C2P);
    Re = r; Im = i;
}
__device__ __forceinline__ void pW8_3c(ull& Re, ull& Im) {
    const ull r = pmul(padd(Re, Im), (ull)CN2P);
    const ull i = pmul(psub(Re, Im), (ull)C2P);
    Re = r; Im = i;
}

// ======================= half-packed complex: one complex per ull (re,im) =======================
typedef ull cplx;
__device__ __forceinline__ cplx cswap(cplx v) { float2 t = unpk(v); return pk2(t.y, t.x); }
__device__ __forceinline__ cplx cmulP(cplx a, float wx, float wy) {
    return pfma(cswap(a), pk2(-wy, wy), pmul(a, splat(wx)));
}
__device__ __forceinline__ cplx cmuljP(cplx a, float wx, float wy) {
    return pfma(cswap(a), pk2(wy, -wy), pmul(a, splat(wx)));
}
__device__ __forceinline__ cplx cmulPC(cplx a, cplx wxx, cplx wyt) {
    return pfma(cswap(a), wyt, pmul(a, wxx));
}
__device__ __forceinline__ cplx rNI(cplx v)   { float2 t = unpk(v); return pk2(t.y, -t.x); }
__device__ __forceinline__ cplx rPI(cplx v)   { float2 t = unpk(v); return pk2(-t.y, t.x); }
__device__ __forceinline__ cplx rW8_1(cplx v) { float2 t = unpk(v); return pk2(RC2 * (t.x + t.y), RC2 * (t.y - t.x)); }
__device__ __forceinline__ cplx rW8_3(cplx v) { float2 t = unpk(v); return pk2(RC2 * (t.y - t.x), -RC2 * (t.x + t.y)); }
__device__ __forceinline__ cplx rW8_1c(cplx v){ float2 t = unpk(v); return pk2(RC2 * (t.x - t.y), RC2 * (t.x + t.y)); }
__device__ __forceinline__ cplx rW8_3c(cplx v){ float2 t = unpk(v); return pk2(-RC2 * (t.x + t.y), RC2 * (t.x - t.y)); }

// ---- half-packed 8-pt DIF (natural -> bitrev slots)
__device__ __forceinline__ void reg_dif8_c(cplx a[8]) {
    cplx t0 = padd(a[0], a[4]), t4 = psub(a[0], a[4]);
    cplx t1 = padd(a[1], a[5]), t5 = rW8_1(psub(a[1], a[5]));
    cplx t2 = padd(a[2], a[6]), t6 = rNI(psub(a[2], a[6]));
    cplx t3 = padd(a[3], a[7]), t7 = rW8_3(psub(a[3], a[7]));
    cplx u0 = padd(t0, t2), u2 = psub(t0, t2);
    cplx u1 = padd(t1, t3), u3 = rNI(psub(t1, t3));
    cplx u4 = padd(t4, t6), u6 = psub(t4, t6);
    cplx u5 = padd(t5, t7), u7 = rNI(psub(t5, t7));
    a[0] = padd(u0, u1); a[1] = psub(u0, u1);
    a[2] = padd(u2, u3); a[3] = psub(u2, u3);
    a[4] = padd(u4, u5); a[5] = psub(u4, u5);
    a[6] = padd(u6, u7); a[7] = psub(u6, u7);
}
// ---- half-packed 8-pt inverse DIT (bitrev slots -> natural)
__device__ __forceinline__ void reg_dit8_inv_c(cplx a[8]) {
    cplx t0 = padd(a[0], a[1]), t1 = psub(a[0], a[1]);
    cplx t2 = padd(a[2], a[3]), t3 = psub(a[2], a[3]);
    cplx t4 = padd(a[4], a[5]), t5 = psub(a[4], a[5]);
    cplx t6 = padd(a[6], a[7]), t7 = psub(a[6], a[7]);
    cplx b;
    cplx u0 = padd(t0, t2), u2 = psub(t0, t2);
    b = rPI(t3);
    cplx u1 = padd(t1, b), u3 = psub(t1, b);
    cplx u4 = padd(t4, t6), u6 = psub(t4, t6);
    b = rPI(t7);
    cplx u5 = padd(t5, b), u7 = psub(t5, b);
    a[0] = padd(u0, u4); a[4] = psub(u0, u4);
    b = rW8_1c(u5);
    a[1] = padd(u1, b); a[5] = psub(u1, b);
    b = rPI(u6);
    a[2] = padd(u2, b); a[6] = psub(u2, b);
    b = rW8_3c(u7);
    a[3] = padd(u3, b); a[7] = psub(u3, b);
}
// ---- half-packed cross-lane 32-pt DIF
__device__ __forceinline__ void xlane_fwd_c(cplx a[8], int lane, const float2 wcl[5]) {
    #pragma unroll
    for (int st = 0; st < 5; ++st) {
        const int m = 16 >> st;
        const bool up = (lane & m) != 0;
        const float wex = up ? wcl[st].x : 1.0f;
        const float wey = up ? wcl[st].y : 0.0f;
        const cplx sgnP = splat(up ? -1.0f : 1.0f);
        const cplx wxx  = splat(wex);
        const cplx wyt  = pk2(-wey, wey);
        #pragma unroll
        for (int i = 0; i < 8; ++i) {
            const cplx o = pshfl_xor(a[i], m);
            const cplx t = pfma(a[i], sgnP, o);     // low: a+o ; up: o-a
            a[i] = cmulPC(t, wxx, wyt);
        }
    }
}
// ---- half-packed cross-lane 32-pt inverse DIT (conj twiddles)
__device__ __forceinline__ void xlane_inv_c(cplx a[8], int lane, const float2 wcl[5]) {
    #pragma unroll
    for (int st = 0; st < 5; ++st) {
        const int m = 1 << st;
        const float2 w = wcl[4 - st];
        const bool up = (lane & m) != 0;
        const float wex = up ? w.x : 1.0f;
        const float wey = up ? -w.y : 0.0f;        // conj
        const cplx sgnP = splat(up ? -1.0f : 1.0f);
        const cplx wxx  = splat(wex);
        const cplx wyt  = pk2(-wey, wey);
        #pragma unroll
        for (int i = 0; i < 8; ++i) {
            const cplx v = cmulPC(a[i], wxx, wyt);
            const cplx o = pshfl_xor(v, m);
            a[i] = pfma(v, sgnP, o);               // low: v+o ; up: o-v
        }
    }
}
__device__ __forceinline__ void twiddle_fwd_c(cplx a[8], const float2 wp[8]) {
    a[1] = cmulP(a[1], wp[4].x, wp[4].y); a[2] = cmulP(a[2], wp[2].x, wp[2].y);
    a[3] = cmulP(a[3], wp[6].x, wp[6].y); a[4] = cmulP(a[4], wp[1].x, wp[1].y);
    a[5] = cmulP(a[5], wp[5].x, wp[5].y); a[6] = cmulP(a[6], wp[3].x, wp[3].y);
    a[7] = cmulP(a[7], wp[7].x, wp[7].y);
}
__device__ __forceinline__ void twiddle_inv_c(cplx a[8], const float2 wp[8]) {
    a[1] = cmuljP(a[1], wp[4].x, wp[4].y); a[2] = cmuljP(a[2], wp[2].x, wp[2].y);
    a[3] = cmuljP(a[3], wp[6].x, wp[6].y); a[4] = cmuljP(a[4], wp[1].x, wp[1].y);
    a[5] = cmuljP(a[5], wp[5].x, wp[5].y); a[6] = cmuljP(a[6], wp[3].x, wp[3].y);
    a[7] = cmuljP(a[7], wp[7].x, wp[7].y);
}
__device__ __forceinline__ void fft256_fwd_c(cplx a[8], int lane, const float2 wp[8], const float2 wcl[5]) {
    reg_dif8_c(a); twiddle_fwd_c(a, wp); xlane_fwd_c(a, lane, wcl);
}
__device__ __forceinline__ void fft256_inv_c(cplx a[8], int lane, const float2 wp[8], const float2 wcl[5]) {
    xlane_inv_c(a, lane, wcl); twiddle_inv_c(a, wp); reg_dit8_inv_c(a);
}

// ======================= mode-packed 256-pt FFT (both modes) =======================
__device__ __forceinline__ void reg_dif8_p(ull R[8], ull I[8]) {
    ull r0 = padd(R[0], R[4]), i0 = padd(I[0], I[4]);
    ull r4 = psub(R[0], R[4]), i4 = psub(I[0], I[4]);
    ull r1 = padd(R[1], R[5]), i1 = padd(I[1], I[5]);
    ull r5 = psub(R[1], R[5]), i5 = psub(I[1], I[5]); pW8_1(r5, i5);
    ull r2 = padd(R[2], R[6]), i2 = padd(I[2], I[6]);
    ull r6 = psub(R[2], R[6]), i6 = psub(I[2], I[6]); pNI(r6, i6);
    ull r3 = padd(R[3], R[7]), i3 = padd(I[3], I[7]);
    ull r7 = psub(R[3], R[7]), i7 = psub(I[3], I[7]); pW8_3(r7, i7);

    ull ur0 = padd(r0, r2), ui0 = padd(i0, i2);
    ull ur2 = psub(r0, r2), ui2 = psub(i0, i2);
    ull ur1 = padd(r1, r3), ui1 = padd(i1, i3);
    ull ur3 = psub(r1, r3), ui3 = psub(i1, i3); pNI(ur3, ui3);
    ull ur4 = padd(r4, r6), ui4 = padd(i4, i6);
    ull ur6 = psub(r4, r6), ui6 = psub(i4, i6);
    ull ur5 = padd(r5, r7), ui5 = padd(i5, i7);
    ull ur7 = psub(r5, r7), ui7 = psub(i5, i7); pNI(ur7, ui7);

    R[0] = padd(ur0, ur1); I[0] = padd(ui0, ui1);
    R[1] = psub(ur0, ur1); I[1] = psub(ui0, ui1);
    R[2] = padd(ur2, ur3); I[2] = padd(ui2, ui3);
    R[3] = psub(ur2, ur3); I[3] = psub(ui2, ui3);
    R[4] = padd(ur4, ur5); I[4] = padd(ui4, ui5);
    R[5] = psub(ur4, ur5); I[5] = psub(ui4, ui5);
    R[6] = padd(ur6, ur7); I[6] = padd(ui6, ui7);
    R[7] = psub(ur6, ur7); I[7] = psub(ui6, ui7);
}
__device__ __forceinline__ void reg_dit8_inv_p(ull R[8], ull I[8]) {
    ull tr0 = padd(R[0], R[1]), ti0 = padd(I[0], I[1]);
    ull tr1 = psub(R[0], R[1]), ti1 = psub(I[0], I[1]);
    ull tr2 = padd(R[2], R[3]), ti2 = padd(I[2], I[3]);
    ull tr3 = psub(R[2], R[3]), ti3 = psub(I[2], I[3]);
    ull tr4 = padd(R[4], R[5]), ti4 = padd(I[4], I[5]);
    ull tr5 = psub(R[4], R[5]), ti5 = psub(I[4], I[5]);
    ull tr6 = padd(R[6], R[7]), ti6 = padd(I[6], I[7]);
    ull tr7 = psub(R[6], R[7]), ti7 = psub(I[6], I[7]);

    ull ur0 = padd(tr0, tr2), ui0 = padd(ti0, ti2);
    ull ur2 = psub(tr0, tr2), ui2 = psub(ti0, ti2);
    pPI(tr3, ti3);
    ull ur1 = padd(tr1, tr3), ui1 = padd(ti1, ti3);
    ull ur3 = psub(tr1, tr3), ui3 = psub(ti1, ti3);
    ull ur4 = padd(tr4, tr6), ui4 = padd(ti4, ti6);
    ull ur6 = psub(tr4, tr6), ui6 = psub(ti4, ti6);
    pPI(tr7, ti7);
    ull ur5 = padd(tr5, tr7), ui5 = padd(ti5, ti7);
    ull ur7 = psub(tr5, tr7), ui7 = psub(ti5, ti7);

    R[0] = padd(ur0, ur4); I[0] = padd(ui0, ui4);
    R[4] = psub(ur0, ur4); I[4] = psub(ui0, ui4);
    pW8_1c(ur5, ui5);
    R[1] = padd(ur1, ur5); I[1] = padd(ui1, ui5);
    R[5] = psub(ur1, ur5); I[5] = psub(ui1, ui5);
    pPI(ur6, ui6);
    R[2] = padd(ur2, ur6); I[2] = padd(ui2, ui6);
    R[6] = psub(ur2, ur6); I[6] = psub(ui2, ui6);
    pW8_3c(ur7, ui7);
    R[3] = padd(ur3, ur7); I[3] = padd(ui3, ui7);
    R[7] = psub(ur3, ur7); I[7] = psub(ui3, ui7);
}
__device__ __forceinline__ void xlane_fwd_p(ull R[8], ull I[8], int lane, const float2 wcl[5]) {
    #pragma unroll
    for (int st = 0; st < 5; ++st) {
        const int m = 16 >> st;
        const bool up = (lane & m) != 0;
        const float wex = up ? wcl[st].x : 1.0f;
        const float wey = up ? wcl[st].y : 0.0f;
        const ull sgnP = splat(up ? -1.0f : 1.0f);
        const ull wxx = splat(wex), wyy = splat(wey), wyn = splat(-wey);
        #pragma unroll
        for (int i = 0; i < 8; ++i) {
            const ull oR = pshfl_xor(R[i], m);
            const ull oI = pshfl_xor(I[i], m);
            const ull tR = pfma(R[i], sgnP, oR);   // low: R+oR ; up: oR-R
            const ull tI = pfma(I[i], sgnP, oI);
            R[i] = pfma(tR, wxx, pmul(tI, wyn));
            I[i] = pfma(tR, wyy, pmul(tI, wxx));
        }
    }
}
__device__ __forceinline__ void xlane_inv_p(ull R[8], ull I[8], int lane, const float2 wcl[5]) {
    #pragma unroll
    for (int st = 0; st < 5; ++st) {
        const int m = 1 << st;
        const float2 w = wcl[4 - st];
        const bool up = (lane & m) != 0;
        const float wex = up ? w.x : 1.0f;
        const float wey = up ? -w.y : 0.0f;        // conj
        const ull sgnP = splat(up ? -1.0f : 1.0f);
        const ull wxx = splat(wex), wyy = splat(wey), wyn = splat(-wey);
        #pragma unroll
        for (int i = 0; i < 8; ++i) {
            const ull vR = pfma(R[i], wxx, pmul(I[i], wyn));
            const ull vI = pfma(R[i], wyy, pmul(I[i], wxx));
            const ull oR = pshfl_xor(vR, m);
            const ull oI = pshfl_xor(vI, m);
            R[i] = pfma(vR, sgnP, oR);
            I[i] = pfma(vI, sgnP, oI);
        }
    }
}
__device__ __forceinline__ void twiddle_fwd_p(ull R[8], ull I[8], const float2 wp[8]) {
    pcmul(R[1], I[1], wp[4].x, wp[4].y); pcmul(R[2], I[2], wp[2].x, wp[2].y);
    pcmul(R[3], I[3], wp[6].x, wp[6].y); pcmul(R[4], I[4], wp[1].x, wp[1].y);
    pcmul(R[5], I[5], wp[5].x, wp[5].y); pcmul(R[6], I[6], wp[3].x, wp[3].y);
    pcmul(R[7], I[7], wp[7].x, wp[7].y);
}
__device__ __forceinline__ void twiddle_inv_p(ull R[8], ull I[8], const float2 wp[8]) {
    pcmul(R[1], I[1], wp[4].x, -wp[4].y); pcmul(R[2], I[2], wp[2].x, -wp[2].y);
    pcmul(R[3], I[3], wp[6].x, -wp[6].y); pcmul(R[4], I[4], wp[1].x, -wp[1].y);
    pcmul(R[5], I[5], wp[5].x, -wp[5].y); pcmul(R[6], I[6], wp[3].x, -wp[3].y);
    pcmul(R[7], I[7], wp[7].x, -wp[7].y);
}
__device__ __forceinline__ void fft256_fwd_p(ull R[8], ull I[8], int lane, const float2 wp[8], const float2 wcl[5]) {
    reg_dif8_p(R, I); twiddle_fwd_p(R, I, wp); xlane_fwd_p(R, I, lane, wcl);
}
__device__ __forceinline__ void fft256_inv_p(ull R[8], ull I[8], int lane, const float2 wp[8], const float2 wcl[5]) {
    xlane_inv_p(R, I, lane, wcl); twiddle_inv_p(R, I, wp); reg_dit8_inv_p(R, I);
}

// ---------------- prologue: block 0 builds C~; blocks >= 1 zero CTA-boundary strips ----------------
__global__ __launch_bounds__(1024) void prologue_kernel(
    const float* __restrict__ h_real,
    const float* __restrict__ h_imag,
    float* __restrict__ out,
    int L, int steps)
{
    const int t = threadIdx.x;
    if (blockIdx.x == 0) {
        __shared__ float2 lut[NFFT];
        __shared__ float hr[MTAPS], hi[MTAPS];
        __shared__ float2 part[1024];
        const int n = t & (NFFT - 1);
        const int g = t >> 8;
        if (t < NFFT) {
            float sn, cs;
            __sincosf(-(TWO_PI_F / NFFT) * (float)n, &sn, &cs);
            lut[n] = make_float2(cs, sn);
        }
        if (t < MTAPS) { hr[t] = h_real[t]; hi[t] = h_imag[t]; }
        __syncthreads();
        const int m0 = g * 11;
        const int m1 = (m0 + 11 < MTAPS) ? (m0 + 11) : MTAPS;
        float sr = 0.0f, si = 0.0f;
        for (int m = m0; m < m1; ++m) {
            const int e = (n * (m - PAD)) & (NFFT - 1);
            const float2 w = lut[e];
            sr = fmaf(hr[m], w.x, fmaf(-hi[m], w.y, sr));
            si = fmaf(hr[m], w.y, fmaf( hi[m], w.x, si));
        }
        part[t] = make_float2(sr, si);
        __syncthreads();
        if (t < NFFT) {
            const float2 p0 = part[t], p1 = part[t + 256], p2 = part[t + 512], p3 = part[t + 768];
            g_C[t] = make_float2((p0.x + p1.x + p2.x + p3.x) * (1.0f / NFFT),
                                 (p0.y + p1.y + p2.y + p3.y) * (1.0f / NFFT));
        }
    } else {
        // Zero only CTA-boundary overlap strips: frames s = 4, 8, ... (< steps)
        const int nb = (steps - 1) >> 2;           // boundaries per batch
        const int per_b = nb * OVERLAP;
        const int idx = (blockIdx.x - 1) * 1024 + t;
        if (idx >= BATCH * per_b) return;
        const int b = (idx >= per_b) ? 1 : 0;
        const int u = idx - b * per_b;
        const int k = u / OVERLAP;
        const int e = u - k * OVERLAP;
        const int sD = 4 * (k + 1);
        const int lp = sD * HOP + e;
        const int Lout = L - OVERLAP;
        reinterpret_cast<float4*>(out)[(size_t)b * Lout + lp - PAD] = make_float4(0.f, 0.f, 0.f, 0.f);
    }
}

// ---------------- kernel 1: 4 consecutive frames/CTA; smem overlap combine; PDL ----------------
__global__ __launch_bounds__(128) void eq_frame_kernel(
    const float* __restrict__ x_real,
    const float* __restrict__ x_imag,
    const float* __restrict__ task_info,
    float* __restrict__ out,
    int L, int steps)
{
    __shared__ float4 s_tail[3][OVERLAP];   // warps 0..2 publish tails here

    const int warp = threadIdx.x >> 5;
    const int s = blockIdx.x * 4 + warp;
    const int lane = threadIdx.x & 31;
    const int b = blockIdx.y;
    const bool active = (s < steps);
    const int Lout = L - OVERLAP;
    float4* outb = reinterpret_cast<float4*>(out) + (size_t)b * Lout + (size_t)s * HOP - PAD;

    float4 v[8];

    if (active) {
        // cross-lane stage twiddles (registers)
        float2 wcl[5];
        #pragma unroll
        for (int st = 0; st < 5; ++st) {
            const int m = 16 >> st;
            const float ang = -(TWO_PI_F / (2.0f * (float)m)) * (float)(lane & (m - 1));
            __sincosf(ang, &wcl[st].y, &wcl[st].x);
        }
        float2 wp[8];
        wp[0] = make_float2(1.0f, 0.0f);
        __sincosf(-(TWO_PI_F / 256.0f) * (float)lane, &wp[1].y, &wp[1].x);
        wp[2] = cmulf(wp[1], wp[1]);
        wp[3] = cmulf(wp[2], wp[1]);
        wp[4] = cmulf(wp[2], wp[2]);
        wp[5] = cmulf(wp[4], wp[1]);
        wp[6] = cmulf(wp[3], wp[3]);
        wp[7] = cmulf(wp[4], wp[3]);

        // ---- load frame
        ull R[8], I[8];
        const ull* xr8 = reinterpret_cast<const ull*>(x_real) + (size_t)b * L;
        const ull* xi8 = reinterpret_cast<const ull*>(x_imag) + (size_t)b * L;
        const int base = s * HOP + lane;
        #pragma unroll
        for (int r = 0; r < 8; ++r) {
            R[r] = __ldg(&xr8[base + 32 * r]);
            I[r] = __ldg(&xi8[base + 32 * r]);
        }

        // ---- forward FFT (both modes)  [independent of prologue]
        fft256_fwd_p(R, I, lane, wp, wcl);

        // ---- intensity per bin
        cplx Iv[8];
        #pragma unroll
        for (int i = 0; i < 8; ++i) {
            const float2 rr = unpk(R[i]);
            const float2 ii = unpk(I[i]);
            float t = rr.x * rr.x;
            t = fmaf(rr.y, rr.y, t);
            t = fmaf(ii.x, ii.x, t);
            t = fmaf(ii.y, ii.y, t);
            Iv[i] = pk2(t, 0.0f);
        }

        // ---- inverse part of phi chain  [independent of prologue]
        fft256_inv_c(Iv, lane, wp, wcl);

        // ==== PDL: wait for the prologue (g_C table + zeroed boundary strips) ====
        cudaGridDependencySynchronize();

        // ---- multiply by C~ and finish phi
        #pragma unroll
        for (int r = 0; r < 8; ++r) {
            const float2 cw = __ldg(&g_C[lane + 32 * r]);
            Iv[r] = cmulP(Iv[r], cw.x, cw.y);
        }
        fft256_fwd_c(Iv, lane, wp, wcl);

        // ---- Y = X * (1 + i*P*phi) * (1/N)
        const float P = exp2f(task_info[b * 4] * 0.33219280948873623f) * 0.5f;  // 10^(x/10)/2
        const float sc = 1.0f / (float)NFFT;
        #pragma unroll
        for (int i = 0; i < 8; ++i) {
            const float2 ph = unpk(Iv[i]);
            const float fx = fmaf(-P, ph.y, 1.0f) * sc;
            const float fy = (P * ph.x) * sc;
            pcmul(R[i], I[i], fx, fy);
        }

        // ---- inverse FFT (both modes) -> natural time order (scaled)
        fft256_inv_p(R, I, lane, wp, wcl);

        #pragma unroll
        for (int r = 0; r < 8; ++r) {
            const float2 rr = unpk(R[r]);
            const float2 ii = unpk(I[r]);
            v[r] = make_float4(rr.x, ii.x, rr.y, ii.y);
        }

        // ---- interior stores: n in [40,216)
        { const int n = 32 + lane; if (lane >= 8) outb[n] = v[1]; }
        outb[64  + lane] = v[2];
        outb[96  + lane] = v[3];
        outb[128 + lane] = v[4];
        { const int n = 192 + lane; if (lane < 24) outb[n] = v[6]; }
        outb[160 + lane] = v[5];

        // ---- tail: n in [216,256)
        if (s == steps - 1) {
            { const int n = 192 + lane; if (lane >= 24) outb[n] = v[6]; }          // n<236 always
            { const int n = 224 + lane; if (n < NFFT - PAD) outb[n] = v[7]; }
        } else if (warp < 3) {
            { const int n = 192 + lane; if (lane >= 24) s_tail[warp][n - HOP] = v[6]; }
            { const int n = 224 + lane; s_tail[warp][n - HOP] = v[7]; }
        } else {
            // CTA boundary: RED 0.5x into the pre-zeroed strip
            { const int n = 192 + lane;
              if (lane >= 24) {
                  float4* p = &outb[n];
                  asm volatile("red.global.add.v4.f32 [%0], {%1, %2, %3, %4};"
                               :: "l"(p), "f"(v[6].x * 0.5f), "f"(v[6].y * 0.5f),
                                  "f"(v[6].z * 0.5f), "f"(v[6].w * 0.5f) : "memory"); } }
            { const int n = 224 + lane;
              float4* p = &outb[n];
              asm volatile("red.global.add.v4.f32 [%0], {%1, %2, %3, %4};"
                           :: "l"(p), "f"(v[7].x * 0.5f), "f"(v[7].y * 0.5f),
                              "f"(v[7].z * 0.5f), "f"(v[7].w * 0.5f) : "memory"); }
        }
    }

    __syncthreads();

    if (active) {
        // ---- head: n in [0,40)
        if (s == 0) {
            { const int n = lane; if (n >= PAD) outb[n] = v[0]; }
            { if (lane < 8) outb[32 + lane] = v[1]; }
        } else if (warp > 0) {
            const float4* tp = s_tail[warp - 1];
            {
                const int n = lane;
                const float4 t = tp[n];
                outb[n] = make_float4((v[0].x + t.x) * 0.5f, (v[0].y + t.y) * 0.5f,
                                      (v[0].z + t.z) * 0.5f, (v[0].w + t.w) * 0.5f);
            }
            if (lane < 8) {
                const int n = 32 + lane;
                const float4 t = tp[n];
                outb[n] = make_float4((v[1].x + t.x) * 0.5f, (v[1].y + t.y) * 0.5f,
                                      (v[1].z + t.z) * 0.5f, (v[1].w + t.w) * 0.5f);
            }
        } else {
            // CTA boundary: RED 0.5x into the pre-zeroed strip
            {
                const int n = lane;
                float4* p = &outb[n];
                asm volatile("red.global.add.v4.f32 [%0], {%1, %2, %3, %4};"
                             :: "l"(p), "f"(v[0].x * 0.5f), "f"(v[0].y * 0.5f),
                                "f"(v[0].z * 0.5f), "f"(v[0].w * 0.5f) : "memory");
            }
            if (lane < 8) {
                const int n = 32 + lane;
                float4* p = &outb[n];
                asm volatile("red.global.add.v4.f32 [%0], {%1, %2, %3, %4};"
                             :: "l"(p), "f"(v[1].x * 0.5f), "f"(v[1].y * 0.5f),
                                "f"(v[1].z * 0.5f), "f"(v[1].w * 0.5f) : "memory");
            }
        }
    }
}

extern "C" void kernel_launch(void* const* d_in, const int* in_sizes, int n_in,
                              void* d_out, int out_size)
{
    const float* x_real    = (const float*)d_in[0];
    const float* x_imag    = (const float*)d_in[1];
    const float* task_info = (const float*)d_in[2];
    const float* h_real    = (const float*)d_in[3];
    const float* h_imag    = (const float*)d_in[4];

    const int L = in_sizes[0] / (BATCH * 2);
    int steps = (L - NFFT) / HOP + 1;
    if (steps > MAX_STEPS) steps = MAX_STEPS;

    const int nb = (steps - 1) >> 2;
    const int strip_total = BATCH * nb * OVERLAP;
    const int zero_blocks = (strip_total + 1023) / 1024;
    prologue_kernel<<<1 + zero_blocks, 1024>>>(h_real, h_imag, (float*)d_out, L, steps);

    dim3 grid((steps + 3) / 4, BATCH);
    cudaLaunchConfig_t cfg = {};
    cfg.gridDim = grid;
    cfg.blockDim = dim3(128, 1, 1);
    cfg.dynamicSmemBytes = 0;
    cfg.stream = 0;
    cudaLaunchAttribute attrs[1];
    attrs[0].id = cudaLaunchAttributeProgrammaticStreamSerialization;
    attrs[0].val.programmaticStreamSerializationAllowed = 1;
    cfg.attrs = attrs;
    cfg.numAttrs = 1;
    cudaLaunchKernelEx(&cfg, eq_frame_kernel, x_real, x_imag, task_info, (float*)d_out, L, steps);
}

// round 16
// speedup vs baseline: 1.0215x; 1.0215x over previous
#include <cuda_runtime.h>
#include <math.h>

#define MTAPS   41
#define OVERLAP 40
#define HOP     216
#define NFFT    256
#define PAD     20
#define BATCH   2
#define MAX_STEPS 4628
#define TWO_PI_F 6.283185307179586f

typedef unsigned long long ull;

__device__ float2 g_C[NFFT];   // C~[n] = (1/256) sum_m h[m] e^{-2 pi i n (m-20)/256}

__device__ __forceinline__ float2 cmulf(float2 a, float2 b) {
    return make_float2(fmaf(-a.y, b.y, a.x * b.x), fmaf(a.y, b.x, a.x * b.y));
}

// ======================= f32x2 packed primitives =======================
__device__ __forceinline__ ull pk2(float x, float y) {
    ull u; asm("mov.b64 %0, {%1,%2};" : "=l"(u) : "f"(x), "f"(y)); return u;
}
__device__ __forceinline__ float2 unpk(ull u) {
    float2 a; asm("mov.b64 {%0,%1}, %2;" : "=f"(a.x), "=f"(a.y) : "l"(u)); return a;
}
__device__ __forceinline__ ull splat(float x) { return pk2(x, x); }
__device__ __forceinline__ ull padd(ull a, ull b) {
    ull r; asm("add.rn.f32x2 %0, %1, %2;" : "=l"(r) : "l"(a), "l"(b)); return r;
}
__device__ __forceinline__ ull psub(ull a, ull b) {
    ull r; asm("sub.rn.f32x2 %0, %1, %2;" : "=l"(r) : "l"(a), "l"(b)); return r;
}
__device__ __forceinline__ ull pmul(ull a, ull b) {
    ull r; asm("mul.rn.f32x2 %0, %1, %2;" : "=l"(r) : "l"(a), "l"(b)); return r;
}
__device__ __forceinline__ ull pfma(ull a, ull b, ull c) {
    ull r; asm("fma.rn.f32x2 %0, %1, %2, %3;" : "=l"(r) : "l"(a), "l"(b), "l"(c)); return r;
}
#define C2P  0x3F3504F33F3504F3ULL
#define CN2P 0xBF3504F3BF3504F3ULL
#define ZP   0x0000000000000000ULL
#define RC2 0.70710678118654752440f

__device__ __forceinline__ ull pneg(ull a) { return psub(ZP, a); }
__device__ __forceinline__ ull pshfl_xor(ull v, int m) {
    unsigned lo = (unsigned)v, hi = (unsigned)(v >> 32);
    lo = __shfl_xor_sync(0xffffffffu, lo, m);
    hi = __shfl_xor_sync(0xffffffffu, hi, m);
    return ((ull)hi << 32) | (ull)lo;
}

// ======================= mode-packed complex (Re-pair, Im-pair) =======================
__device__ __forceinline__ void pcmul(ull& Re, ull& Im, float wx, float wy) {
    const ull sx = splat(wx), sy = splat(wy), syn = splat(-wy);
    const ull r = pfma(Re, sx, pmul(Im, syn));
    const ull i = pfma(Re, sy, pmul(Im, sx));
    Re = r; Im = i;
}
__device__ __forceinline__ void pW8_1(ull& Re, ull& Im) {
    const ull r = pmul(padd(Re, Im), (ull)C2P);
    const ull i = pmul(psub(Im, Re), (ull)C2P);
    Re = r; Im = i;
}
__device__ __forceinline__ void pW8_3(ull& Re, ull& Im) {
    const ull r = pmul(psub(Im, Re), (ull)C2P);
    const ull i = pmul(padd(Re, Im), (ull)CN2P);
    Re = r; Im = i;
}
__device__ __forceinline__ void pNI(ull& Re, ull& Im) { const ull r = Im; const ull i = pneg(Re); Re = r; Im = i; }
__device__ __forceinline__ void pPI(ull& Re, ull& Im) { const ull r = pneg(Im); const ull i = Re; Re = r; Im = i; }
__device__ __forceinline__ void pW8_1c(ull& Re, ull& Im) {
    const ull r = pmul(psub(Re, Im), (ull)C2P);
    const ull i = pmul(padd(Re, Im), (ull)C2P);
    Re = r; Im = i;
}
__device__ __forceinline__ void pW8_3c(ull& Re, ull& Im) {
    const ull r = pmul(padd(Re, Im), (ull)CN2P);
    const ull i = pmul(psub(Re, Im), (ull)C2P);
    Re = r; Im = i;
}

// ======================= half-packed complex: one complex per ull (re,im) =======================
typedef ull cplx;
__device__ __forceinline__ cplx cswap(cplx v) { float2 t = unpk(v); return pk2(t.y, t.x); }
__device__ __forceinline__ cplx cmulP(cplx a, float wx, float wy) {
    return pfma(cswap(a), pk2(-wy, wy), pmul(a, splat(wx)));
}
__device__ __forceinline__ cplx cmuljP(cplx a, float wx, float wy) {
    return pfma(cswap(a), pk2(wy, -wy), pmul(a, splat(wx)));
}
__device__ __forceinline__ cplx cmulPC(cplx a, cplx wxx, cplx wyt) {
    return pfma(cswap(a), wyt, pmul(a, wxx));
}
__device__ __forceinline__ cplx rNI(cplx v)   { float2 t = unpk(v); return pk2(t.y, -t.x); }
__device__ __forceinline__ cplx rPI(cplx v)   { float2 t = unpk(v); return pk2(-t.y, t.x); }
__device__ __forceinline__ cplx rW8_1(cplx v) { float2 t = unpk(v); return pk2(RC2 * (t.x + t.y), RC2 * (t.y - t.x)); }
__device__ __forceinline__ cplx rW8_3(cplx v) { float2 t = unpk(v); return pk2(RC2 * (t.y - t.x), -RC2 * (t.x + t.y)); }
__device__ __forceinline__ cplx rW8_1c(cplx v){ float2 t = unpk(v); return pk2(RC2 * (t.x - t.y), RC2 * (t.x + t.y)); }
__device__ __forceinline__ cplx rW8_3c(cplx v){ float2 t = unpk(v); return pk2(-RC2 * (t.x + t.y), RC2 * (t.x - t.y)); }

// ---- half-packed 8-pt DIF (natural -> bitrev slots)
__device__ __forceinline__ void reg_dif8_c(cplx a[8]) {
    cplx t0 = padd(a[0], a[4]), t4 = psub(a[0], a[4]);
    cplx t1 = padd(a[1], a[5]), t5 = rW8_1(psub(a[1], a[5]));
    cplx t2 = padd(a[2], a[6]), t6 = rNI(psub(a[2], a[6]));
    cplx t3 = padd(a[3], a[7]), t7 = rW8_3(psub(a[3], a[7]));
    cplx u0 = padd(t0, t2), u2 = psub(t0, t2);
    cplx u1 = padd(t1, t3), u3 = rNI(psub(t1, t3));
    cplx u4 = padd(t4, t6), u6 = psub(t4, t6);
    cplx u5 = padd(t5, t7), u7 = rNI(psub(t5, t7));
    a[0] = padd(u0, u1); a[1] = psub(u0, u1);
    a[2] = padd(u2, u3); a[3] = psub(u2, u3);
    a[4] = padd(u4, u5); a[5] = psub(u4, u5);
    a[6] = padd(u6, u7); a[7] = psub(u6, u7);
}
// ---- half-packed 8-pt inverse DIT (bitrev slots -> natural)
__device__ __forceinline__ void reg_dit8_inv_c(cplx a[8]) {
    cplx t0 = padd(a[0], a[1]), t1 = psub(a[0], a[1]);
    cplx t2 = padd(a[2], a[3]), t3 = psub(a[2], a[3]);
    cplx t4 = padd(a[4], a[5]), t5 = psub(a[4], a[5]);
    cplx t6 = padd(a[6], a[7]), t7 = psub(a[6], a[7]);
    cplx b;
    cplx u0 = padd(t0, t2), u2 = psub(t0, t2);
    b = rPI(t3);
    cplx u1 = padd(t1, b), u3 = psub(t1, b);
    cplx u4 = padd(t4, t6), u6 = psub(t4, t6);
    b = rPI(t7);
    cplx u5 = padd(t5, b), u7 = psub(t5, b);
    a[0] = padd(u0, u4); a[4] = psub(u0, u4);
    b = rW8_1c(u5);
    a[1] = padd(u1, b); a[5] = psub(u1, b);
    b = rPI(u6);
    a[2] = padd(u2, b); a[6] = psub(u2, b);
    b = rW8_3c(u7);
    a[3] = padd(u3, b); a[7] = psub(u3, b);
}
// ---- half-packed cross-lane 32-pt DIF
__device__ __forceinline__ void xlane_fwd_c(cplx a[8], int lane, const float2 wcl[5]) {
    #pragma unroll
    for (int st = 0; st < 5; ++st) {
        const int m = 16 >> st;
        const bool up = (lane & m) != 0;
        const float wex = up ? wcl[st].x : 1.0f;
        const float wey = up ? wcl[st].y : 0.0f;
        const cplx sgnP = splat(up ? -1.0f : 1.0f);
        const cplx wxx  = splat(wex);
        const cplx wyt  = pk2(-wey, wey);
        #pragma unroll
        for (int i = 0; i < 8; ++i) {
            const cplx o = pshfl_xor(a[i], m);
            const cplx t = pfma(a[i], sgnP, o);     // low: a+o ; up: o-a
            a[i] = cmulPC(t, wxx, wyt);
        }
    }
}
// ---- half-packed cross-lane 32-pt inverse DIT (conj twiddles)
__device__ __forceinline__ void xlane_inv_c(cplx a[8], int lane, const float2 wcl[5]) {
    #pragma unroll
    for (int st = 0; st < 5; ++st) {
        const int m = 1 << st;
        const float2 w = wcl[4 - st];
        const bool up = (lane & m) != 0;
        const float wex = up ? w.x : 1.0f;
        const float wey = up ? -w.y : 0.0f;        // conj
        const cplx sgnP = splat(up ? -1.0f : 1.0f);
        const cplx wxx  = splat(wex);
        const cplx wyt  = pk2(-wey, wey);
        #pragma unroll
        for (int i = 0; i < 8; ++i) {
            const cplx v = cmulPC(a[i], wxx, wyt);
            const cplx o = pshfl_xor(v, m);
            a[i] = pfma(v, sgnP, o);               // low: v+o ; up: o-v
        }
    }
}
__device__ __forceinline__ void twiddle_fwd_c(cplx a[8], const float2 wp[8]) {
    a[1] = cmulP(a[1], wp[4].x, wp[4].y); a[2] = cmulP(a[2], wp[2].x, wp[2].y);
    a[3] = cmulP(a[3], wp[6].x, wp[6].y); a[4] = cmulP(a[4], wp[1].x, wp[1].y);
    a[5] = cmulP(a[5], wp[5].x, wp[5].y); a[6] = cmulP(a[6], wp[3].x, wp[3].y);
    a[7] = cmulP(a[7], wp[7].x, wp[7].y);
}
__device__ __forceinline__ void twiddle_inv_c(cplx a[8], const float2 wp[8]) {
    a[1] = cmuljP(a[1], wp[4].x, wp[4].y); a[2] = cmuljP(a[2], wp[2].x, wp[2].y);
    a[3] = cmuljP(a[3], wp[6].x, wp[6].y); a[4] = cmuljP(a[4], wp[1].x, wp[1].y);
    a[5] = cmuljP(a[5], wp[5].x, wp[5].y); a[6] = cmuljP(a[6], wp[3].x, wp[3].y);
    a[7] = cmuljP(a[7], wp[7].x, wp[7].y);
}
__device__ __forceinline__ void fft256_fwd_c(cplx a[8], int lane, const float2 wp[8], const float2 wcl[5]) {
    reg_dif8_c(a); twiddle_fwd_c(a, wp); xlane_fwd_c(a, lane, wcl);
}
__device__ __forceinline__ void fft256_inv_c(cplx a[8], int lane, const float2 wp[8], const float2 wcl[5]) {
    xlane_inv_c(a, lane, wcl); twiddle_inv_c(a, wp); reg_dit8_inv_c(a);
}

// ======================= mode-packed 256-pt FFT (both modes) =======================
__device__ __forceinline__ void reg_dif8_p(ull R[8], ull I[8]) {
    ull r0 = padd(R[0], R[4]), i0 = padd(I[0], I[4]);
    ull r4 = psub(R[0], R[4]), i4 = psub(I[0], I[4]);
    ull r1 = padd(R[1], R[5]), i1 = padd(I[1], I[5]);
    ull r5 = psub(R[1], R[5]), i5 = psub(I[1], I[5]); pW8_1(r5, i5);
    ull r2 = padd(R[2], R[6]), i2 = padd(I[2], I[6]);
    ull r6 = psub(R[2], R[6]), i6 = psub(I[2], I[6]); pNI(r6, i6);
    ull r3 = padd(R[3], R[7]), i3 = padd(I[3], I[7]);
    ull r7 = psub(R[3], R[7]), i7 = psub(I[3], I[7]); pW8_3(r7, i7);

    ull ur0 = padd(r0, r2), ui0 = padd(i0, i2);
    ull ur2 = psub(r0, r2), ui2 = psub(i0, i2);
    ull ur1 = padd(r1, r3), ui1 = padd(i1, i3);
    ull ur3 = psub(r1, r3), ui3 = psub(i1, i3); pNI(ur3, ui3);
    ull ur4 = padd(r4, r6), ui4 = padd(i4, i6);
    ull ur6 = psub(r4, r6), ui6 = psub(i4, i6);
    ull ur5 = padd(r5, r7), ui5 = padd(i5, i7);
    ull ur7 = psub(r5, r7), ui7 = psub(i5, i7); pNI(ur7, ui7);

    R[0] = padd(ur0, ur1); I[0] = padd(ui0, ui1);
    R[1] = psub(ur0, ur1); I[1] = psub(ui0, ui1);
    R[2] = padd(ur2, ur3); I[2] = padd(ui2, ui3);
    R[3] = psub(ur2, ur3); I[3] = psub(ui2, ui3);
    R[4] = padd(ur4, ur5); I[4] = padd(ui4, ui5);
    R[5] = psub(ur4, ur5); I[5] = psub(ui4, ui5);
    R[6] = padd(ur6, ur7); I[6] = padd(ui6, ui7);
    R[7] = psub(ur6, ur7); I[7] = psub(ui6, ui7);
}
__device__ __forceinline__ void reg_dit8_inv_p(ull R[8], ull I[8]) {
    ull tr0 = padd(R[0], R[1]), ti0 = padd(I[0], I[1]);
    ull tr1 = psub(R[0], R[1]), ti1 = psub(I[0], I[1]);
    ull tr2 = padd(R[2], R[3]), ti2 = padd(I[2], I[3]);
    ull tr3 = psub(R[2], R[3]), ti3 = psub(I[2], I[3]);
    ull tr4 = padd(R[4], R[5]), ti4 = padd(I[4], I[5]);
    ull tr5 = psub(R[4], R[5]), ti5 = psub(I[4], I[5]);
    ull tr6 = padd(R[6], R[7]), ti6 = padd(I[6], I[7]);
    ull tr7 = psub(R[6], R[7]), ti7 = psub(I[6], I[7]);

    ull ur0 = padd(tr0, tr2), ui0 = padd(ti0, ti2);
    ull ur2 = psub(tr0, tr2), ui2 = psub(ti0, ti2);
    pPI(tr3, ti3);
    ull ur1 = padd(tr1, tr3), ui1 = padd(ti1, ti3);
    ull ur3 = psub(tr1, tr3), ui3 = psub(ti1, ti3);
    ull ur4 = padd(tr4, tr6), ui4 = padd(ti4, ti6);
    ull ur6 = psub(tr4, tr6), ui6 = psub(ti4, ti6);
    pPI(tr7, ti7);
    ull ur5 = padd(tr5, tr7), ui5 = padd(ti5, ti7);
    ull ur7 = psub(tr5, tr7), ui7 = psub(ti5, ti7);

    R[0] = padd(ur0, ur4); I[0] = padd(ui0, ui4);
    R[4] = psub(ur0, ur4); I[4] = psub(ui0, ui4);
    pW8_1c(ur5, ui5);
    R[1] = padd(ur1, ur5); I[1] = padd(ui1, ui5);
    R[5] = psub(ur1, ur5); I[5] = psub(ui1, ui5);
    pPI(ur6, ui6);
    R[2] = padd(ur2, ur6); I[2] = padd(ui2, ui6);
    R[6] = psub(ur2, ur6); I[6] = psub(ui2, ui6);
    pW8_3c(ur7, ui7);
    R[3] = padd(ur3, ur7); I[3] = padd(ui3, ui7);
    R[7] = psub(ur3, ur7); I[7] = psub(ui3, ui7);
}
__device__ __forceinline__ void xlane_fwd_p(ull R[8], ull I[8], int lane, const float2 wcl[5]) {
    #pragma unroll
    for (int st = 0; st < 5; ++st) {
        const int m = 16 >> st;
        const bool up = (lane & m) != 0;
        const float wex = up ? wcl[st].x : 1.0f;
        const float wey = up ? wcl[st].y : 0.0f;
        const ull sgnP = splat(up ? -1.0f : 1.0f);
        const ull wxx = splat(wex), wyy = splat(wey), wyn = splat(-wey);
        #pragma unroll
        for (int i = 0; i < 8; ++i) {
            const ull oR = pshfl_xor(R[i], m);
            const ull oI = pshfl_xor(I[i], m);
            const ull tR = pfma(R[i], sgnP, oR);   // low: R+oR ; up: oR-R
            const ull tI = pfma(I[i], sgnP, oI);
            R[i] = pfma(tR, wxx, pmul(tI, wyn));
            I[i] = pfma(tR, wyy, pmul(tI, wxx));
        }
    }
}
__device__ __forceinline__ void xlane_inv_p(ull R[8], ull I[8], int lane, const float2 wcl[5]) {
    #pragma unroll
    for (int st = 0; st < 5; ++st) {
        const int m = 1 << st;
        const float2 w = wcl[4 - st];
        const bool up = (lane & m) != 0;
        const float wex = up ? w.x : 1.0f;
        const float wey = up ? -w.y : 0.0f;        // conj
        const ull sgnP = splat(up ? -1.0f : 1.0f);
        const ull wxx = splat(wex), wyy = splat(wey), wyn = splat(-wey);
        #pragma unroll
        for (int i = 0; i < 8; ++i) {
            const ull vR = pfma(R[i], wxx, pmul(I[i], wyn));
            const ull vI = pfma(R[i], wyy, pmul(I[i], wxx));
            const ull oR = pshfl_xor(vR, m);
            const ull oI = pshfl_xor(vI, m);
            R[i] = pfma(vR, sgnP, oR);
            I[i] = pfma(vI, sgnP, oI);
        }
    }
}
__device__ __forceinline__ void twiddle_fwd_p(ull R[8], ull I[8], const float2 wp[8]) {
    pcmul(R[1], I[1], wp[4].x, wp[4].y); pcmul(R[2], I[2], wp[2].x, wp[2].y);
    pcmul(R[3], I[3], wp[6].x, wp[6].y); pcmul(R[4], I[4], wp[1].x, wp[1].y);
    pcmul(R[5], I[5], wp[5].x, wp[5].y); pcmul(R[6], I[6], wp[3].x, wp[3].y);
    pcmul(R[7], I[7], wp[7].x, wp[7].y);
}
__device__ __forceinline__ void twiddle_inv_p(ull R[8], ull I[8], const float2 wp[8]) {
    pcmul(R[1], I[1], wp[4].x, -wp[4].y); pcmul(R[2], I[2], wp[2].x, -wp[2].y);
    pcmul(R[3], I[3], wp[6].x, -wp[6].y); pcmul(R[4], I[4], wp[1].x, -wp[1].y);
    pcmul(R[5], I[5], wp[5].x, -wp[5].y); pcmul(R[6], I[6], wp[3].x, -wp[3].y);
    pcmul(R[7], I[7], wp[7].x, -wp[7].y);
}
__device__ __forceinline__ void fft256_fwd_p(ull R[8], ull I[8], int lane, const float2 wp[8], const float2 wcl[5]) {
    reg_dif8_p(R, I); twiddle_fwd_p(R, I, wp); xlane_fwd_p(R, I, lane, wcl);
}
__device__ __forceinline__ void fft256_inv_p(ull R[8], ull I[8], int lane, const float2 wp[8], const float2 wcl[5]) {
    xlane_inv_p(R, I, lane, wcl); twiddle_inv_p(R, I, wp); reg_dit8_inv_p(R, I);
}

// ---------------- prologue (small footprint): block 0 builds C~; blocks >= 1 zero strips grid-stride ----------------
#define ZBLOCKS 96
__global__ __launch_bounds__(256) void prologue_kernel(
    const float* __restrict__ h_real,
    const float* __restrict__ h_imag,
    float* __restrict__ out,
    int L, int steps)
{
    const int t = threadIdx.x;
    if (blockIdx.x == 0) {
        __shared__ float2 lut[NFFT];
        __shared__ float hr[MTAPS], hi[MTAPS];
        float sn, cs;
        __sincosf(-(TWO_PI_F / NFFT) * (float)t, &sn, &cs);
        lut[t] = make_float2(cs, sn);
        if (t < MTAPS) { hr[t] = h_real[t]; hi[t] = h_imag[t]; }
        __syncthreads();
        float sr = 0.0f, si = 0.0f;
        #pragma unroll
        for (int m = 0; m < MTAPS; ++m) {
            const int e = (t * (m - PAD)) & (NFFT - 1);
            const float2 w = lut[e];
            sr = fmaf(hr[m], w.x, fmaf(-hi[m], w.y, sr));
            si = fmaf(hr[m], w.y, fmaf( hi[m], w.x, si));
        }
        g_C[t] = make_float2(sr * (1.0f / NFFT), si * (1.0f / NFFT));
    } else {
        // grid-stride zero of overlap strips: for s = 1..steps-1, lp = s*HOP + e, e in [0, OVERLAP)
        const int per_b = (steps - 1) * OVERLAP;
        const int total = BATCH * per_b;
        const int stride = ZBLOCKS * 256;
        const int Lout = L - OVERLAP;
        const float4 z = make_float4(0.f, 0.f, 0.f, 0.f);
        for (int idx = (blockIdx.x - 1) * 256 + t; idx < total; idx += stride) {
            const int b = (idx >= per_b) ? 1 : 0;
            const int u = idx - b * per_b;
            const int s = u / OVERLAP;
            const int e = u - s * OVERLAP;
            const int lp = (s + 1) * HOP + e;
            reinterpret_cast<float4*>(out)[(size_t)b * Lout + lp - PAD] = z;
        }
    }
}

// ---------------- kernel 1: warp per frame, PDL overlap with prologue (R14 version) ----------------
__global__ __launch_bounds__(128) void eq_frame_kernel(
    const float* __restrict__ x_real,
    const float* __restrict__ x_imag,
    const float* __restrict__ task_info,
    float* __restrict__ out,
    int L, int steps)
{
    const int s = blockIdx.x * 4 + (threadIdx.x >> 5);
    const int lane = threadIdx.x & 31;
    const int b = blockIdx.y;

    if (s < steps) {
        // cross-lane stage twiddles (registers)
        float2 wcl[5];
        #pragma unroll
        for (int st = 0; st < 5; ++st) {
            const int m = 16 >> st;
            const float ang = -(TWO_PI_F / (2.0f * (float)m)) * (float)(lane & (m - 1));
            __sincosf(ang, &wcl[st].y, &wcl[st].x);
        }
        // per-lane twiddle powers
        float2 wp[8];
        wp[0] = make_float2(1.0f, 0.0f);
        __sincosf(-(TWO_PI_F / 256.0f) * (float)lane, &wp[1].y, &wp[1].x);
        wp[2] = cmulf(wp[1], wp[1]);
        wp[3] = cmulf(wp[2], wp[1]);
        wp[4] = cmulf(wp[2], wp[2]);
        wp[5] = cmulf(wp[4], wp[1]);
        wp[6] = cmulf(wp[3], wp[3]);
        wp[7] = cmulf(wp[4], wp[3]);

        // ---- load frame: packed Re = (re_mode0, re_mode1), Im likewise
        ull R[8], I[8];
        const ull* xr8 = reinterpret_cast<const ull*>(x_real) + (size_t)b * L;
        const ull* xi8 = reinterpret_cast<const ull*>(x_imag) + (size_t)b * L;
        const int base = s * HOP + lane;
        #pragma unroll
        for (int r = 0; r < 8; ++r) {
            R[r] = __ldg(&xr8[base + 32 * r]);
            I[r] = __ldg(&xi8[base + 32 * r]);
        }

        // ---- forward FFT (both modes at once)  [independent of prologue]
        fft256_fwd_p(R, I, lane, wp, wcl);

        // ---- intensity per bin (half-packed complex: (t, 0))
        cplx Iv[8];
        #pragma unroll
        for (int i = 0; i < 8; ++i) {
            const float2 rr = unpk(R[i]);
            const float2 ii = unpk(I[i]);
            float t = rr.x * rr.x;
            t = fmaf(rr.y, rr.y, t);
            t = fmaf(ii.x, ii.x, t);
            t = fmaf(ii.y, ii.y, t);
            Iv[i] = pk2(t, 0.0f);
        }

        // ---- inverse part of the phi chain  [independent of prologue]
        fft256_inv_c(Iv, lane, wp, wcl);

        // ==== PDL: wait for the prologue (g_C table + zeroed strips) ====
        cudaGridDependencySynchronize();

        // ---- multiply by C~ and finish phi
        #pragma unroll
        for (int r = 0; r < 8; ++r) {
            const float2 cw = __ldg(&g_C[lane + 32 * r]);
            Iv[r] = cmulP(Iv[r], cw.x, cw.y);
        }
        fft256_fwd_c(Iv, lane, wp, wcl);

        // ---- Y = X * (1 + i*P*phi) * (1/N)
        const float P = exp2f(task_info[b * 4] * 0.33219280948873623f) * 0.5f;  // 10^(x/10)/2
        const float sc = 1.0f / (float)NFFT;
        #pragma unroll
        for (int i = 0; i < 8; ++i) {
            const float2 ph = unpk(Iv[i]);
            const float fx = fmaf(-P, ph.y, 1.0f) * sc;
            const float fy = (P * ph.x) * sc;
            pcmul(R[i], I[i], fx, fy);
        }

        // ---- inverse FFT (both modes) -> natural time order (already scaled)
        fft256_inv_p(R, I, lane, wp, wcl);

        // ---- write: interior direct; overlap edges via vector RED into pre-zeroed strips
        const int Lout = L - OVERLAP;
        float4* out4 = reinterpret_cast<float4*>(out) + (size_t)b * Lout;
        #pragma unroll
        for (int r = 0; r < 8; ++r) {
            const int n = lane + 32 * r;
            const float2 rr = unpk(R[r]);
            const float2 ii = unpk(I[r]);
            const int lp = s * HOP + n;
            const bool head = (n < OVERLAP) && (s > 0);
            const bool tail = (n >= HOP) && (s < steps - 1);
            if (head || tail) {
                float4* p = &out4[lp - PAD];
                asm volatile("red.global.add.v4.f32 [%0], {%1, %2, %3, %4};"
                             :: "l"(p), "f"(rr.x * 0.5f), "f"(ii.x * 0.5f),
                                "f"(rr.y * 0.5f), "f"(ii.y * 0.5f)
                             : "memory");
            } else if (lp >= PAD && lp < L - PAD) {
                float4 v;
                v.x = rr.x; v.y = ii.x;   // mode0 (re, im)
                v.z = rr.y; v.w = ii.y;   // mode1 (re, im)
                out4[lp - PAD] = v;
            }
        }
    }
}

extern "C" void kernel_launch(void* const* d_in, const int* in_sizes, int n_in,
                              void* d_out, int out_size)
{
    const float* x_real    = (const float*)d_in[0];
    const float* x_imag    = (const float*)d_in[1];
    const float* task_info = (const float*)d_in[2];
    const float* h_real    = (const float*)d_in[3];
    const float* h_imag    = (const float*)d_in[4];

    const int L = in_sizes[0] / (BATCH * 2);
    int steps = (L - NFFT) / HOP + 1;
    if (steps > MAX_STEPS) steps = MAX_STEPS;

    // Small-footprint prologue: 97 CTAs x 256 threads so eq blocks can co-schedule under PDL.
    prologue_kernel<<<1 + ZBLOCKS, 256>>>(h_real, h_imag, (float*)d_out, L, steps);

    dim3 grid((steps + 3) / 4, BATCH);
    cudaLaunchConfig_t cfg = {};
    cfg.gridDim = grid;
    cfg.blockDim = dim3(128, 1, 1);
    cfg.dynamicSmemBytes = 0;
    cfg.stream = 0;
    cudaLaunchAttribute attrs[1];
    attrs[0].id = cudaLaunchAttributeProgrammaticStreamSerialization;
    attrs[0].val.programmaticStreamSerializationAllowed = 1;
    cfg.attrs = attrs;
    cfg.numAttrs = 1;
    cudaLaunchKernelEx(&cfg, eq_frame_kernel, x_real, x_imag, task_info, (float*)d_out, L, steps);
}

// round 17
// speedup vs baseline: 1.0640x; 1.0417x over previous
#include <cuda_runtime.h>
#include <math.h>

#define MTAPS   41
#define OVERLAP 40
#define HOP     216
#define NFFT    256
#define PAD     20
#define BATCH   2
#define MAX_STEPS 4628
#define TWO_PI_F 6.283185307179586f

typedef unsigned long long ull;

__device__ float2 g_C[NFFT];   // C~[n] = (1/256) sum_m h[m] e^{-2 pi i n (m-20)/256}

__device__ __forceinline__ float2 cmulf(float2 a, float2 b) {
    return make_float2(fmaf(-a.y, b.y, a.x * b.x), fmaf(a.y, b.x, a.x * b.y));
}

// ======================= f32x2 packed primitives =======================
__device__ __forceinline__ ull pk2(float x, float y) {
    ull u; asm("mov.b64 %0, {%1,%2};" : "=l"(u) : "f"(x), "f"(y)); return u;
}
__device__ __forceinline__ float2 unpk(ull u) {
    float2 a; asm("mov.b64 {%0,%1}, %2;" : "=f"(a.x), "=f"(a.y) : "l"(u)); return a;
}
__device__ __forceinline__ ull splat(float x) { return pk2(x, x); }
__device__ __forceinline__ ull padd(ull a, ull b) {
    ull r; asm("add.rn.f32x2 %0, %1, %2;" : "=l"(r) : "l"(a), "l"(b)); return r;
}
__device__ __forceinline__ ull psub(ull a, ull b) {
    ull r; asm("sub.rn.f32x2 %0, %1, %2;" : "=l"(r) : "l"(a), "l"(b)); return r;
}
__device__ __forceinline__ ull pmul(ull a, ull b) {
    ull r; asm("mul.rn.f32x2 %0, %1, %2;" : "=l"(r) : "l"(a), "l"(b)); return r;
}
__device__ __forceinline__ ull pfma(ull a, ull b, ull c) {
    ull r; asm("fma.rn.f32x2 %0, %1, %2, %3;" : "=l"(r) : "l"(a), "l"(b), "l"(c)); return r;
}
#define C2P  0x3F3504F33F3504F3ULL
#define CN2P 0xBF3504F3BF3504F3ULL
#define ZP   0x0000000000000000ULL
#define RC2 0.70710678118654752440f

__device__ __forceinline__ ull pneg(ull a) { return psub(ZP, a); }
__device__ __forceinline__ ull pshfl_xor(ull v, int m) {
    unsigned lo = (unsigned)v, hi = (unsigned)(v >> 32);
    lo = __shfl_xor_sync(0xffffffffu, lo, m);
    hi = __shfl_xor_sync(0xffffffffu, hi, m);
    return ((ull)hi << 32) | (ull)lo;
}

// ======================= mode-packed complex (Re-pair, Im-pair) =======================
__device__ __forceinline__ void pcmul(ull& Re, ull& Im, float wx, float wy) {
    const ull sx = splat(wx), sy = splat(wy), syn = splat(-wy);
    const ull r = pfma(Re, sx, pmul(Im, syn));
    const ull i = pfma(Re, sy, pmul(Im, sx));
    Re = r; Im = i;
}
__device__ __forceinline__ void pW8_1(ull& Re, ull& Im) {
    const ull r = pmul(padd(Re, Im), (ull)C2P);
    const ull i = pmul(psub(Im, Re), (ull)C2P);
    Re = r; Im = i;
}
__device__ __forceinline__ void pW8_3(ull& Re, ull& Im) {
    const ull r = pmul(psub(Im, Re), (ull)C2P);
    const ull i = pmul(padd(Re, Im), (ull)CN2P);
    Re = r; Im = i;
}
__device__ __forceinline__ void pNI(ull& Re, ull& Im) { const ull r = Im; const ull i = pneg(Re); Re = r; Im = i; }
__device__ __forceinline__ void pPI(ull& Re, ull& Im) { const ull r = pneg(Im); const ull i = Re; Re = r; Im = i; }
__device__ __forceinline__ void pW8_1c(ull& Re, ull& Im) {
    const ull r = pmul(psub(Re, Im), (ull)C2P);
    const ull i = pmul(padd(Re, Im), (ull)C2P);
    Re = r; Im = i;
}
__device__ __forceinline__ void pW8_3c(ull& Re, ull& Im) {
    const ull r = pmul(padd(Re, Im), (ull)CN2P);
    const ull i = pmul(psub(Re, Im), (ull)C2P);
    Re = r; Im = i;
}

// ======================= half-packed complex: one complex per ull (re,im) =======================
typedef ull cplx;
__device__ __forceinline__ cplx cswap(cplx v) { float2 t = unpk(v); return pk2(t.y, t.x); }
__device__ __forceinline__ cplx cmulP(cplx a, float wx, float wy) {
    return pfma(cswap(a), pk2(-wy, wy), pmul(a, splat(wx)));
}
__device__ __forceinline__ cplx cmuljP(cplx a, float wx, float wy) {
    return pfma(cswap(a), pk2(wy, -wy), pmul(a, splat(wx)));
}
__device__ __forceinline__ cplx cmulPC(cplx a, cplx wxx, cplx wyt) {
    return pfma(cswap(a), wyt, pmul(a, wxx));
}
__device__ __forceinline__ cplx rNI(cplx v)   { float2 t = unpk(v); return pk2(t.y, -t.x); }
__device__ __forceinline__ cplx rPI(cplx v)   { float2 t = unpk(v); return pk2(-t.y, t.x); }
__device__ __forceinline__ cplx rW8_1(cplx v) { float2 t = unpk(v); return pk2(RC2 * (t.x + t.y), RC2 * (t.y - t.x)); }
__device__ __forceinline__ cplx rW8_3(cplx v) { float2 t = unpk(v); return pk2(RC2 * (t.y - t.x), -RC2 * (t.x + t.y)); }
__device__ __forceinline__ cplx rW8_1c(cplx v){ float2 t = unpk(v); return pk2(RC2 * (t.x - t.y), RC2 * (t.x + t.y)); }
__device__ __forceinline__ cplx rW8_3c(cplx v){ float2 t = unpk(v); return pk2(-RC2 * (t.x + t.y), RC2 * (t.x - t.y)); }

// ---- half-packed 8-pt DIF (natural -> bitrev slots)
__device__ __forceinline__ void reg_dif8_c(cplx a[8]) {
    cplx t0 = padd(a[0], a[4]), t4 = psub(a[0], a[4]);
    cplx t1 = padd(a[1], a[5]), t5 = rW8_1(psub(a[1], a[5]));
    cplx t2 = padd(a[2], a[6]), t6 = rNI(psub(a[2], a[6]));
    cplx t3 = padd(a[3], a[7]), t7 = rW8_3(psub(a[3], a[7]));
    cplx u0 = padd(t0, t2), u2 = psub(t0, t2);
    cplx u1 = padd(t1, t3), u3 = rNI(psub(t1, t3));
    cplx u4 = padd(t4, t6), u6 = psub(t4, t6);
    cplx u5 = padd(t5, t7), u7 = rNI(psub(t5, t7));
    a[0] = padd(u0, u1); a[1] = psub(u0, u1);
    a[2] = padd(u2, u3); a[3] = psub(u2, u3);
    a[4] = padd(u4, u5); a[5] = psub(u4, u5);
    a[6] = padd(u6, u7); a[7] = psub(u6, u7);
}
// ---- half-packed 8-pt inverse DIT (bitrev slots -> natural)
__device__ __forceinline__ void reg_dit8_inv_c(cplx a[8]) {
    cplx t0 = padd(a[0], a[1]), t1 = psub(a[0], a[1]);
    cplx t2 = padd(a[2], a[3]), t3 = psub(a[2], a[3]);
    cplx t4 = padd(a[4], a[5]), t5 = psub(a[4], a[5]);
    cplx t6 = padd(a[6], a[7]), t7 = psub(a[6], a[7]);
    cplx b;
    cplx u0 = padd(t0, t2), u2 = psub(t0, t2);
    b = rPI(t3);
    cplx u1 = padd(t1, b), u3 = psub(t1, b);
    cplx u4 = padd(t4, t6), u6 = psub(t4, t6);
    b = rPI(t7);
    cplx u5 = padd(t5, b), u7 = psub(t5, b);
    a[0] = padd(u0, u4); a[4] = psub(u0, u4);
    b = rW8_1c(u5);
    a[1] = padd(u1, b); a[5] = psub(u1, b);
    b = rPI(u6);
    a[2] = padd(u2, b); a[6] = psub(u2, b);
    b = rW8_3c(u7);
    a[3] = padd(u3, b); a[7] = psub(u3, b);
}
// ---- half-packed cross-lane 32-pt DIF
__device__ __forceinline__ void xlane_fwd_c(cplx a[8], int lane, const float2 wcl[5]) {
    #pragma unroll
    for (int st = 0; st < 5; ++st) {
        const int m = 16 >> st;
        const bool up = (lane & m) != 0;
        const float wex = up ? wcl[st].x : 1.0f;
        const float wey = up ? wcl[st].y : 0.0f;
        const cplx sgnP = splat(up ? -1.0f : 1.0f);
        const cplx wxx  = splat(wex);
        const cplx wyt  = pk2(-wey, wey);
        #pragma unroll
        for (int i = 0; i < 8; ++i) {
            const cplx o = pshfl_xor(a[i], m);
            const cplx t = pfma(a[i], sgnP, o);     // low: a+o ; up: o-a
            a[i] = cmulPC(t, wxx, wyt);
        }
    }
}
// ---- half-packed cross-lane 32-pt inverse DIT (conj twiddles)
// First stage specialized for REAL input (imag = 0): v = a*conj(w) with a.im=0
__device__ __forceinline__ void xlane_inv_c_realin(cplx a[8], int lane, const float2 wcl[5]) {
    // stage st=0, m=1: inputs are (re, 0)
    {
        const float2 w = wcl[4];
        const bool up = (lane & 1) != 0;
        const float wex = up ? w.x : 1.0f;
        const float wey = up ? -w.y : 0.0f;        // conj
        const cplx sgnP = splat(up ? -1.0f : 1.0f);
        const cplx wv   = pk2(wex, wey);
        #pragma unroll
        for (int i = 0; i < 8; ++i) {
            const float re = unpk(a[i]).x;          // imag is zero
            const cplx v = pmul(splat(re), wv);     // (re*wex, re*wey)
            const cplx o = pshfl_xor(v, 1);
            a[i] = pfma(v, sgnP, o);
        }
    }
    #pragma unroll
    for (int st = 1; st < 5; ++st) {
        const int m = 1 << st;
        const float2 w = wcl[4 - st];
        const bool up = (lane & m) != 0;
        const float wex = up ? w.x : 1.0f;
        const float wey = up ? -w.y : 0.0f;        // conj
        const cplx sgnP = splat(up ? -1.0f : 1.0f);
        const cplx wxx  = splat(wex);
        const cplx wyt  = pk2(-wey, wey);
        #pragma unroll
        for (int i = 0; i < 8; ++i) {
            const cplx v = cmulPC(a[i], wxx, wyt);
            const cplx o = pshfl_xor(v, m);
            a[i] = pfma(v, sgnP, o);               // low: v+o ; up: o-v
        }
    }
}
__device__ __forceinline__ void twiddle_fwd_c(cplx a[8], const float2 wp[8]) {
    a[1] = cmulP(a[1], wp[4].x, wp[4].y); a[2] = cmulP(a[2], wp[2].x, wp[2].y);
    a[3] = cmulP(a[3], wp[6].x, wp[6].y); a[4] = cmulP(a[4], wp[1].x, wp[1].y);
    a[5] = cmulP(a[5], wp[5].x, wp[5].y); a[6] = cmulP(a[6], wp[3].x, wp[3].y);
    a[7] = cmulP(a[7], wp[7].x, wp[7].y);
}
__device__ __forceinline__ void twiddle_inv_c(cplx a[8], const float2 wp[8]) {
    a[1] = cmuljP(a[1], wp[4].x, wp[4].y); a[2] = cmuljP(a[2], wp[2].x, wp[2].y);
    a[3] = cmuljP(a[3], wp[6].x, wp[6].y); a[4] = cmuljP(a[4], wp[1].x, wp[1].y);
    a[5] = cmuljP(a[5], wp[5].x, wp[5].y); a[6] = cmuljP(a[6], wp[3].x, wp[3].y);
    a[7] = cmuljP(a[7], wp[7].x, wp[7].y);
}
__device__ __forceinline__ void fft256_fwd_c(cplx a[8], int lane, const float2 wp[8], const float2 wcl[5]) {
    reg_dif8_c(a); twiddle_fwd_c(a, wp); xlane_fwd_c(a, lane, wcl);
}
__device__ __forceinline__ void fft256_inv_c_realin(cplx a[8], int lane, const float2 wp[8], const float2 wcl[5]) {
    xlane_inv_c_realin(a, lane, wcl); twiddle_inv_c(a, wp); reg_dit8_inv_c(a);
}

// ======================= mode-packed 256-pt FFT (both modes) =======================
__device__ __forceinline__ void reg_dif8_p(ull R[8], ull I[8]) {
    ull r0 = padd(R[0], R[4]), i0 = padd(I[0], I[4]);
    ull r4 = psub(R[0], R[4]), i4 = psub(I[0], I[4]);
    ull r1 = padd(R[1], R[5]), i1 = padd(I[1], I[5]);
    ull r5 = psub(R[1], R[5]), i5 = psub(I[1], I[5]); pW8_1(r5, i5);
    ull r2 = padd(R[2], R[6]), i2 = padd(I[2], I[6]);
    ull r6 = psub(R[2], R[6]), i6 = psub(I[2], I[6]); pNI(r6, i6);
    ull r3 = padd(R[3], R[7]), i3 = padd(I[3], I[7]);
    ull r7 = psub(R[3], R[7]), i7 = psub(I[3], I[7]); pW8_3(r7, i7);

    ull ur0 = padd(r0, r2), ui0 = padd(i0, i2);
    ull ur2 = psub(r0, r2), ui2 = psub(i0, i2);
    ull ur1 = padd(r1, r3), ui1 = padd(i1, i3);
    ull ur3 = psub(r1, r3), ui3 = psub(i1, i3); pNI(ur3, ui3);
    ull ur4 = padd(r4, r6), ui4 = padd(i4, i6);
    ull ur6 = psub(r4, r6), ui6 = psub(i4, i6);
    ull ur5 = padd(r5, r7), ui5 = padd(i5, i7);
    ull ur7 = psub(r5, r7), ui7 = psub(i5, i7); pNI(ur7, ui7);

    R[0] = padd(ur0, ur1); I[0] = padd(ui0, ui1);
    R[1] = psub(ur0, ur1); I[1] = psub(ui0, ui1);
    R[2] = padd(ur2, ur3); I[2] = padd(ui2, ui3);
    R[3] = psub(ur2, ur3); I[3] = psub(ui2, ui3);
    R[4] = padd(ur4, ur5); I[4] = padd(ui4, ui5);
    R[5] = psub(ur4, ur5); I[5] = psub(ui4, ui5);
    R[6] = padd(ur6, ur7); I[6] = padd(ui6, ui7);
    R[7] = psub(ur6, ur7); I[7] = psub(ui6, ui7);
}
__device__ __forceinline__ void reg_dit8_inv_p(ull R[8], ull I[8]) {
    ull tr0 = padd(R[0], R[1]), ti0 = padd(I[0], I[1]);
    ull tr1 = psub(R[0], R[1]), ti1 = psub(I[0], I[1]);
    ull tr2 = padd(R[2], R[3]), ti2 = padd(I[2], I[3]);
    ull tr3 = psub(R[2], R[3]), ti3 = psub(I[2], I[3]);
    ull tr4 = padd(R[4], R[5]), ti4 = padd(I[4], I[5]);
    ull tr5 = psub(R[4], R[5]), ti5 = psub(I[4], I[5]);
    ull tr6 = padd(R[6], R[7]), ti6 = padd(I[6], I[7]);
    ull tr7 = psub(R[6], R[7]), ti7 = psub(I[6], I[7]);

    ull ur0 = padd(tr0, tr2), ui0 = padd(ti0, ti2);
    ull ur2 = psub(tr0, tr2), ui2 = psub(ti0, ti2);
    pPI(tr3, ti3);
    ull ur1 = padd(tr1, tr3), ui1 = padd(ti1, ti3);
    ull ur3 = psub(tr1, tr3), ui3 = psub(ti1, ti3);
    ull ur4 = padd(tr4, tr6), ui4 = padd(ti4, ti6);
    ull ur6 = psub(tr4, tr6), ui6 = psub(ti4, ti6);
    pPI(tr7, ti7);
    ull ur5 = padd(tr5, tr7), ui5 = padd(ti5, ti7);
    ull ur7 = psub(tr5, tr7), ui7 = psub(ti5, ti7);

    R[0] = padd(ur0, ur4); I[0] = padd(ui0, ui4);
    R[4] = psub(ur0, ur4); I[4] = psub(ui0, ui4);
    pW8_1c(ur5, ui5);
    R[1] = padd(ur1, ur5); I[1] = padd(ui1, ui5);
    R[5] = psub(ur1, ur5); I[5] = psub(ui1, ui5);
    pPI(ur6, ui6);
    R[2] = padd(ur2, ur6); I[2] = padd(ui2, ui6);
    R[6] = psub(ur2, ur6); I[6] = psub(ui2, ui6);
    pW8_3c(ur7, ui7);
    R[3] = padd(ur3, ur7); I[3] = padd(ui3, ui7);
    R[7] = psub(ur3, ur7); I[7] = psub(ui3, ui7);
}
__device__ __forceinline__ void xlane_fwd_p(ull R[8], ull I[8], int lane, const float2 wcl[5]) {
    #pragma unroll
    for (int st = 0; st < 5; ++st) {
        const int m = 16 >> st;
        const bool up = (lane & m) != 0;
        const float wex = up ? wcl[st].x : 1.0f;
        const float wey = up ? wcl[st].y : 0.0f;
        const ull sgnP = splat(up ? -1.0f : 1.0f);
        const ull wxx = splat(wex), wyy = splat(wey), wyn = splat(-wey);
        #pragma unroll
        for (int i = 0; i < 8; ++i) {
            const ull oR = pshfl_xor(R[i], m);
            const ull oI = pshfl_xor(I[i], m);
            const ull tR = pfma(R[i], sgnP, oR);   // low: R+oR ; up: oR-R
            const ull tI = pfma(I[i], sgnP, oI);
            R[i] = pfma(tR, wxx, pmul(tI, wyn));
            I[i] = pfma(tR, wyy, pmul(tI, wxx));
        }
    }
}
__device__ __forceinline__ void xlane_inv_p(ull R[8], ull I[8], int lane, const float2 wcl[5]) {
    #pragma unroll
    for (int st = 0; st < 5; ++st) {
        const int m = 1 << st;
        const float2 w = wcl[4 - st];
        const bool up = (lane & m) != 0;
        const float wex = up ? w.x : 1.0f;
        const float wey = up ? -w.y : 0.0f;        // conj
        const ull sgnP = splat(up ? -1.0f : 1.0f);
        const ull wxx = splat(wex), wyy = splat(wey), wyn = splat(-wey);
        #pragma unroll
        for (int i = 0; i < 8; ++i) {
            const ull vR = pfma(R[i], wxx, pmul(I[i], wyn));
            const ull vI = pfma(R[i], wyy, pmul(I[i], wxx));
            const ull oR = pshfl_xor(vR, m);
            const ull oI = pshfl_xor(vI, m);
            R[i] = pfma(vR, sgnP, oR);
            I[i] = pfma(vI, sgnP, oI);
        }
    }
}
__device__ __forceinline__ void twiddle_fwd_p(ull R[8], ull I[8], const float2 wp[8]) {
    pcmul(R[1], I[1], wp[4].x, wp[4].y); pcmul(R[2], I[2], wp[2].x, wp[2].y);
    pcmul(R[3], I[3], wp[6].x, wp[6].y); pcmul(R[4], I[4], wp[1].x, wp[1].y);
    pcmul(R[5], I[5], wp[5].x, wp[5].y); pcmul(R[6], I[6], wp[3].x, wp[3].y);
    pcmul(R[7], I[7], wp[7].x, wp[7].y);
}
__device__ __forceinline__ void twiddle_inv_p(ull R[8], ull I[8], const float2 wp[8]) {
    pcmul(R[1], I[1], wp[4].x, -wp[4].y); pcmul(R[2], I[2], wp[2].x, -wp[2].y);
    pcmul(R[3], I[3], wp[6].x, -wp[6].y); pcmul(R[4], I[4], wp[1].x, -wp[1].y);
    pcmul(R[5], I[5], wp[5].x, -wp[5].y); pcmul(R[6], I[6], wp[3].x, -wp[3].y);
    pcmul(R[7], I[7], wp[7].x, -wp[7].y);
}
__device__ __forceinline__ void fft256_fwd_p(ull R[8], ull I[8], int lane, const float2 wp[8], const float2 wcl[5]) {
    reg_dif8_p(R, I); twiddle_fwd_p(R, I, wp); xlane_fwd_p(R, I, lane, wcl);
}
__device__ __forceinline__ void fft256_inv_p(ull R[8], ull I[8], int lane, const float2 wp[8], const float2 wcl[5]) {
    xlane_inv_p(R, I, lane, wcl); twiddle_inv_p(R, I, wp); reg_dit8_inv_p(R, I);
}

// ---------------- prologue (small footprint, early PDL trigger) ----------------
#define ZBLOCKS 96
__global__ __launch_bounds__(256) void prologue_kernel(
    const float* __restrict__ h_real,
    const float* __restrict__ h_imag,
    float* __restrict__ out,
    int L, int steps)
{
    // Let the dependent eq_frame grid start launching immediately; its
    // cudaGridDependencySynchronize() still waits for our memory to be visible.
    cudaTriggerProgrammaticLaunchCompletion();

    const int t = threadIdx.x;
    if (blockIdx.x == 0) {
        __shared__ float2 lut[NFFT];
        __shared__ float hr[MTAPS], hi[MTAPS];
        float sn, cs;
        __sincosf(-(TWO_PI_F / NFFT) * (float)t, &sn, &cs);
        lut[t] = make_float2(cs, sn);
        if (t < MTAPS) { hr[t] = h_real[t]; hi[t] = h_imag[t]; }
        __syncthreads();
        float sr = 0.0f, si = 0.0f;
        #pragma unroll
        for (int m = 0; m < MTAPS; ++m) {
            const int e = (t * (m - PAD)) & (NFFT - 1);
            const float2 w = lut[e];
            sr = fmaf(hr[m], w.x, fmaf(-hi[m], w.y, sr));
            si = fmaf(hr[m], w.y, fmaf( hi[m], w.x, si));
        }
        g_C[t] = make_float2(sr * (1.0f / NFFT), si * (1.0f / NFFT));
    } else {
        // grid-stride zero of overlap strips: for s = 1..steps-1, lp = s*HOP + e, e in [0, OVERLAP)
        const int per_b = (steps - 1) * OVERLAP;
        const int total = BATCH * per_b;
        const int stride = ZBLOCKS * 256;
        const int Lout = L - OVERLAP;
        const float4 z = make_float4(0.f, 0.f, 0.f, 0.f);
        for (int idx = (blockIdx.x - 1) * 256 + t; idx < total; idx += stride) {
            const int b = (idx >= per_b) ? 1 : 0;
            const int u = idx - b * per_b;
            const int s = u / OVERLAP;
            const int e = u - s * OVERLAP;
            const int lp = (s + 1) * HOP + e;
            reinterpret_cast<float4*>(out)[(size_t)b * Lout + lp - PAD] = z;
        }
    }
}

// ---------------- kernel 1: warp per frame, PDL overlap with prologue ----------------
__global__ __launch_bounds__(128) void eq_frame_kernel(
    const float* __restrict__ x_real,
    const float* __restrict__ x_imag,
    const float* __restrict__ task_info,
    float* __restrict__ out,
    int L, int steps)
{
    const int s = blockIdx.x * 4 + (threadIdx.x >> 5);
    const int lane = threadIdx.x & 31;
    const int b = blockIdx.y;

    if (s < steps) {
        // cross-lane stage twiddles (registers)
        float2 wcl[5];
        #pragma unroll
        for (int st = 0; st < 5; ++st) {
            const int m = 16 >> st;
            const float ang = -(TWO_PI_F / (2.0f * (float)m)) * (float)(lane & (m - 1));
            __sincosf(ang, &wcl[st].y, &wcl[st].x);
        }
        // per-lane twiddle powers
        float2 wp[8];
        wp[0] = make_float2(1.0f, 0.0f);
        __sincosf(-(TWO_PI_F / 256.0f) * (float)lane, &wp[1].y, &wp[1].x);
        wp[2] = cmulf(wp[1], wp[1]);
        wp[3] = cmulf(wp[2], wp[1]);
        wp[4] = cmulf(wp[2], wp[2]);
        wp[5] = cmulf(wp[4], wp[1]);
        wp[6] = cmulf(wp[3], wp[3]);
        wp[7] = cmulf(wp[4], wp[3]);

        // ---- load frame: packed Re = (re_mode0, re_mode1), Im likewise
        ull R[8], I[8];
        const ull* xr8 = reinterpret_cast<const ull*>(x_real) + (size_t)b * L;
        const ull* xi8 = reinterpret_cast<const ull*>(x_imag) + (size_t)b * L;
        const int base = s * HOP + lane;
        #pragma unroll
        for (int r = 0; r < 8; ++r) {
            R[r] = __ldg(&xr8[base + 32 * r]);
            I[r] = __ldg(&xi8[base + 32 * r]);
        }

        // ---- forward FFT (both modes at once)  [independent of prologue]
        fft256_fwd_p(R, I, lane, wp, wcl);

        // ---- intensity per bin (half-packed complex: (t, 0))
        cplx Iv[8];
        #pragma unroll
        for (int i = 0; i < 8; ++i) {
            const float2 rr = unpk(R[i]);
            const float2 ii = unpk(I[i]);
            float t = rr.x * rr.x;
            t = fmaf(rr.y, rr.y, t);
            t = fmaf(ii.x, ii.x, t);
            t = fmaf(ii.y, ii.y, t);
            Iv[i] = pk2(t, 0.0f);
        }

        // ---- inverse part of the phi chain (real-input specialized)  [independent of prologue]
        fft256_inv_c_realin(Iv, lane, wp, wcl);

        // ==== PDL: wait for the prologue (g_C table + zeroed strips) ====
        cudaGridDependencySynchronize();

        // ---- multiply by C~ and finish phi
        #pragma unroll
        for (int r = 0; r < 8; ++r) {
            const float2 cw = __ldg(&g_C[lane + 32 * r]);
            Iv[r] = cmulP(Iv[r], cw.x, cw.y);
        }
        fft256_fwd_c(Iv, lane, wp, wcl);

        // ---- Y = X * (1 + i*P*phi) * (1/N)
        const float P = exp2f(task_info[b * 4] * 0.33219280948873623f) * 0.5f;  // 10^(x/10)/2
        const float sc = 1.0f / (float)NFFT;
        #pragma unroll
        for (int i = 0; i < 8; ++i) {
            const float2 ph = unpk(Iv[i]);
            const float fx = fmaf(-P, ph.y, 1.0f) * sc;
            const float fy = (P * ph.x) * sc;
            pcmul(R[i], I[i], fx, fy);
        }

        // ---- inverse FFT (both modes) -> natural time order (already scaled)
        fft256_inv_p(R, I, lane, wp, wcl);

        // ---- write: interior direct; overlap edges via vector RED into pre-zeroed strips
        const int Lout = L - OVERLAP;
        float4* out4 = reinterpret_cast<float4*>(out) + (size_t)b * Lout;
        #pragma unroll
        for (int r = 0; r < 8; ++r) {
            const int n = lane + 32 * r;
            const float2 rr = unpk(R[r]);
            const float2 ii = unpk(I[r]);
            const int lp = s * HOP + n;
            const bool head = (n < OVERLAP) && (s > 0);
            const bool tail = (n >= HOP) && (s < steps - 1);
            if (head || tail) {
                float4* p = &out4[lp - PAD];
                asm volatile("red.global.add.v4.f32 [%0], {%1, %2, %3, %4};"
                             :: "l"(p), "f"(rr.x * 0.5f), "f"(ii.x * 0.5f),
                                "f"(rr.y * 0.5f), "f"(ii.y * 0.5f)
                             : "memory");
            } else if (lp >= PAD && lp < L - PAD) {
                float4 v;
                v.x = rr.x; v.y = ii.x;   // mode0 (re, im)
                v.z = rr.y; v.w = ii.y;   // mode1 (re, im)
                out4[lp - PAD] = v;
            }
        }
    }
}

extern "C" void kernel_launch(void* const* d_in, const int* in_sizes, int n_in,
                              void* d_out, int out_size)
{
    const float* x_real    = (const float*)d_in[0];
    const float* x_imag    = (const float*)d_in[1];
    const float* task_info = (const float*)d_in[2];
    const float* h_real    = (const float*)d_in[3];
    const float* h_imag    = (const float*)d_in[4];

    const int L = in_sizes[0] / (BATCH * 2);
    int steps = (L - NFFT) / HOP + 1;
    if (steps > MAX_STEPS) steps = MAX_STEPS;

    // Small-footprint prologue with early programmatic trigger.
    prologue_kernel<<<1 + ZBLOCKS, 256>>>(h_real, h_imag, (float*)d_out, L, steps);

    dim3 grid((steps + 3) / 4, BATCH);
    cudaLaunchConfig_t cfg = {};
    cfg.gridDim = grid;
    cfg.blockDim = dim3(128, 1, 1);
    cfg.dynamicSmemBytes = 0;
    cfg.stream = 0;
    cudaLaunchAttribute attrs[1];
    attrs[0].id = cudaLaunchAttributeProgrammaticStreamSerialization;
    attrs[0].val.programmaticStreamSerializationAllowed = 1;
    cfg.attrs = attrs;
    cfg.numAttrs = 1;
    cudaLaunchKernelEx(&cfg, eq_frame_kernel, x_real, x_imag, task_info, (float*)d_out, L, steps);
}